// round 9
// baseline (speedup 1.0000x reference)
#include <cuda_runtime.h>
#include <math.h>
#include <stdint.h>

#define NB 2
#define NTOK 4096

__device__ float g_Pqc[8192*512];
__device__ float g_Pqs[8192*512];
__device__ float g_Pkc[8192*512];
__device__ float g_Pvc[8192*512];
__device__ float g_Pks[8192*512];   // stored column-permuted within 8-groups
__device__ float g_Pvs[8192*128];
__device__ float g_Sca[16*16*64*64];
__device__ float g_Pca[16*64*64];
__device__ float g_ts [8192*512];
__device__ float g_tsh[8192*512];
__device__ float g_th [8192*128];
__device__ float g_tWqc[512*512];
__device__ float g_tWqs[512*512];
__device__ float g_tWkc[512*512];
__device__ float g_tWvc[512*512];
__device__ float g_tWks[512*512];
__device__ float g_tWvs[128*128];

// =================== helpers ===================
__device__ __forceinline__ uint32_t f2tf(float x) {
    uint32_t r; asm("cvt.rna.tf32.f32 %0, %1;" : "=r"(r) : "f"(x)); return r;
}
__device__ __forceinline__ float ex2f(float x) {
    float r; asm("ex2.approx.ftz.f32 %0, %1;" : "=f"(r) : "f"(x)); return r;
}
__device__ __forceinline__ void mma8(float* d, const uint32_t* a, uint32_t b0, uint32_t b1) {
    asm volatile(
        "mma.sync.aligned.m16n8k8.row.col.f32.tf32.tf32.f32 "
        "{%0,%1,%2,%3},{%4,%5,%6,%7},{%8,%9},{%0,%1,%2,%3};"
        : "+f"(d[0]), "+f"(d[1]), "+f"(d[2]), "+f"(d[3])
        : "r"(a[0]), "r"(a[1]), "r"(a[2]), "r"(a[3]), "r"(b0), "r"(b1));
}
__device__ __forceinline__ uint32_t smem_u32(const void* p) {
    uint32_t a;
    asm("{ .reg .u64 t; cvta.to.shared.u64 t, %1; cvt.u32.u64 %0, t; }" : "=r"(a) : "l"(p));
    return a;
}
__device__ __forceinline__ void cpasync16(uint32_t dst, const void* src) {
    asm volatile("cp.async.ca.shared.global [%0], [%1], 16;" :: "r"(dst), "l"(src));
}
#define CP_COMMIT() asm volatile("cp.async.commit_group;" ::: "memory")
#define CP_WAIT1()  asm volatile("cp.async.wait_group 1;" ::: "memory")
#define CP_WAIT0()  asm volatile("cp.async.wait_group 0;" ::: "memory")

// =================== prep: round all inputs to tf32 once ===================
#define SEG0 1048576
#define SEG1 2097152
#define SEG2 2359296
#define SEG3 2424832
#define SEG4 2490368
#define SEG5 2555904
#define SEG6 2621440
#define SEG7 2686976
#define SEGT 2691072
__global__ __launch_bounds__(256) void prep(
    const float4* __restrict__ s, const float4* __restrict__ sh, const float4* __restrict__ h,
    const float4* __restrict__ wqc, const float4* __restrict__ wqs, const float4* __restrict__ wkc,
    const float4* __restrict__ wvc, const float4* __restrict__ wks, const float4* __restrict__ wvs)
{
    int i = blockIdx.x * blockDim.x + threadIdx.x;
    if (i >= SEGT) return;
    const float4* src; float4* dst; int off;
    if      (i < SEG0) { src = s;   dst = (float4*)g_ts;   off = i; }
    else if (i < SEG1) { src = sh;  dst = (float4*)g_tsh;  off = i - SEG0; }
    else if (i < SEG2) { src = h;   dst = (float4*)g_th;   off = i - SEG1; }
    else if (i < SEG3) { src = wqc; dst = (float4*)g_tWqc; off = i - SEG2; }
    else if (i < SEG4) { src = wqs; dst = (float4*)g_tWqs; off = i - SEG3; }
    else if (i < SEG5) { src = wkc; dst = (float4*)g_tWkc; off = i - SEG4; }
    else if (i < SEG6) { src = wvc; dst = (float4*)g_tWvc; off = i - SEG5; }
    else if (i < SEG7) { src = wks; dst = (float4*)g_tWks; off = i - SEG6; }
    else               { src = wvs; dst = (float4*)g_tWvs; off = i - SEG7; }
    float4 v = src[off];
    dst[off] = make_float4(__uint_as_float(f2tf(v.x)), __uint_as_float(f2tf(v.y)),
                           __uint_as_float(f2tf(v.z)), __uint_as_float(f2tf(v.w)));
}

// =================== tf32 TC GEMM, 3-stage cp.async ===================
#define GSTG 2560
#define GSMEM (3*GSTG*2*4)

template<int K, int O>
__device__ __forceinline__ void gemm_tc_tile(const float* __restrict__ A,
                                             const float* __restrict__ W,
                                             float* __restrict__ C,
                                             int m0, int o0, int mode,
                                             float* dynsm)
{
    const int NC = K / 16;
    float* sA = dynsm;
    float* sW = dynsm + 3*GSTG;
    int tid = threadIdx.x, w = tid >> 5, lane = tid & 31;
    int g = lane >> 2, tg = lane & 3;
    int wm = w >> 2, wn = w & 3;
    int pr = tid >> 1, pc = (tid & 1) << 3;
    const float* Ap = A + (size_t)(m0 + pr) * K + pc;
    const float* Wp = W + (size_t)(o0 + pr) * K + pc;
    uint32_t sAb[3], sWb[3];
    #pragma unroll
    for (int st = 0; st < 3; st++) {
        sAb[st] = smem_u32(sA + st*GSTG + pr*20 + pc);
        sWb[st] = smem_u32(sW + st*GSTG + pr*20 + pc);
    }

    float acc[4][4][4];
    #pragma unroll
    for (int mt = 0; mt < 4; mt++)
        #pragma unroll
        for (int nt = 0; nt < 4; nt++)
            #pragma unroll
            for (int e = 0; e < 4; e++) acc[mt][nt][e] = 0.f;

    cpasync16(sAb[0],      Ap);      cpasync16(sAb[0] + 16, Ap + 4);
    cpasync16(sWb[0],      Wp);      cpasync16(sWb[0] + 16, Wp + 4);
    CP_COMMIT();
    cpasync16(sAb[1],      Ap + 16); cpasync16(sAb[1] + 16, Ap + 20);
    cpasync16(sWb[1],      Wp + 16); cpasync16(sWb[1] + 16, Wp + 20);
    CP_COMMIT();

    #pragma unroll 1
    for (int c = 0; c < NC; c++) {
        if (c + 1 < NC) { CP_WAIT1(); } else { CP_WAIT0(); }
        __syncthreads();
        if (c + 2 < NC) {
            int st = (c + 2) % 3;
            const float* ap = Ap + (c+2)*16;
            const float* wp = Wp + (c+2)*16;
            cpasync16(sAb[st],      ap); cpasync16(sAb[st] + 16, ap + 4);
            cpasync16(sWb[st],      wp); cpasync16(sWb[st] + 16, wp + 4);
            CP_COMMIT();
        }
        int st = c % 3;
        const uint32_t* cA = (const uint32_t*)(sA + st*GSTG);
        const uint32_t* cW = (const uint32_t*)(sW + st*GSTG);
        #pragma unroll
        for (int ks = 0; ks < 2; ks++) {
            uint32_t af[4][4], bf[4][2];
            #pragma unroll
            for (int mt = 0; mt < 4; mt++) {
                int rb = wm*64 + mt*16;
                af[mt][0] = cA[(rb+g  )*20 + ks*8 + tg];
                af[mt][1] = cA[(rb+g+8)*20 + ks*8 + tg];
                af[mt][2] = cA[(rb+g  )*20 + ks*8 + tg + 4];
                af[mt][3] = cA[(rb+g+8)*20 + ks*8 + tg + 4];
            }
            #pragma unroll
            for (int nt = 0; nt < 4; nt++) {
                int rb = wn*32 + nt*8 + g;
                bf[nt][0] = cW[rb*20 + ks*8 + tg];
                bf[nt][1] = cW[rb*20 + ks*8 + tg + 4];
            }
            #pragma unroll
            for (int mt = 0; mt < 4; mt++)
                #pragma unroll
                for (int nt = 0; nt < 4; nt++)
                    mma8(acc[mt][nt], af[mt], bf[nt][0], bf[nt][1]);
        }
    }
    int pc0 = (tg < 2) ? 4*tg     : 4*tg - 7;
    int pc1 = (tg < 2) ? 4*tg + 2 : 4*tg - 5;
    #pragma unroll
    for (int mt = 0; mt < 4; mt++) {
        int r = m0 + wm*64 + mt*16 + g;
        #pragma unroll
        for (int nt = 0; nt < 4; nt++) {
            float v0 = acc[mt][nt][0], v1 = acc[mt][nt][1];
            float v2 = acc[mt][nt][2], v3 = acc[mt][nt][3];
            if (mode != 0) {
                v0 = __uint_as_float(f2tf(v0)); v1 = __uint_as_float(f2tf(v1));
                v2 = __uint_as_float(f2tf(v2)); v3 = __uint_as_float(f2tf(v3));
            }
            float* cp = C + (size_t)r*O + o0 + wn*32 + nt*8;
            if (mode == 2) {
                cp[pc0]       = v0; cp[pc1]       = v1;
                cp[8*O + pc0] = v2; cp[8*O + pc1] = v3;
            } else {
                *(float2*)(cp + 2*tg)       = make_float2(v0, v1);
                *(float2*)(cp + 8*O + 2*tg) = make_float2(v2, v3);
            }
        }
    }
}

__global__ __launch_bounds__(256, 2) void gemm_proj_tc()
{
    extern __shared__ float gdsm[];
    int job = blockIdx.x >> 2;
    int ot  = blockIdx.x & 3;
    int m0  = blockIdx.y << 7;
    const float* A; const float* W; float* C; int mode;
    switch (job) {
        case 0: A = g_tsh; W = g_tWqs; C = g_Pqs; mode = 1; break;
        case 1: A = g_tsh; W = g_tWkc; C = g_Pkc; mode = 0; break;
        case 2: A = g_tsh; W = g_tWvc; C = g_Pvc; mode = 0; break;
        case 3: A = g_tsh; W = g_tWks; C = g_Pks; mode = 2; break;
        default: A = g_ts; W = g_tWqc; C = g_Pqc; mode = 0; break;
    }
    gemm_tc_tile<512,512>(A, W, C, m0, ot << 7, mode, gdsm);
}

__global__ __launch_bounds__(256, 2) void gemm_vs_tc()
{
    extern __shared__ float gdsm[];
    gemm_tc_tile<128,128>(g_th, g_tWvs, g_Pvs, blockIdx.x << 7, 0, 1, gdsm);
}

// =================== channel attention (fp32, unchanged) ===================
__global__ __launch_bounds__(256) void ca_scores()
{
    __shared__ float Qs[32][68];
    __shared__ float Ks[32][68];
    int slice = blockIdx.x;
    int bh    = blockIdx.y;
    int b = bh >> 3, h = bh & 7;
    const float* Qc = g_Pqc + ((size_t)b*NTOK + h*512) * 512;
    const float* Kc = g_Pkc + ((size_t)b*NTOK + h*512) * 512;
    int tid = threadIdx.x;
    int lr = tid >> 3, lc = (tid & 7) << 3;
    int i0 = (tid >> 4) << 2, j0 = (tid & 15) << 2;
    float acc[4][4];
    #pragma unroll
    for (int i = 0; i < 4; i++)
        #pragma unroll
        for (int j = 0; j < 4; j++) acc[i][j] = 0.f;
    #pragma unroll 1
    for (int nt = 0; nt < 8; nt++) {
        int nb = slice*256 + (nt << 5);
        const float* qp = Qc + (size_t)(nb + lr)*64 + lc;
        const float* kp = Kc + (size_t)(nb + lr)*64 + lc;
        float4 q0 = *(const float4*)qp, q1 = *(const float4*)(qp+4);
        float4 k0 = *(const float4*)kp, k1 = *(const float4*)(kp+4);
        __syncthreads();
        *(float4*)&Qs[lr][lc] = q0; *(float4*)&Qs[lr][lc+4] = q1;
        *(float4*)&Ks[lr][lc] = k0; *(float4*)&Ks[lr][lc+4] = k1;
        __syncthreads();
        #pragma unroll 8
        for (int nn = 0; nn < 32; nn++) {
            float4 q = *(const float4*)&Qs[nn][i0];
            float4 k = *(const float4*)&Ks[nn][j0];
            float qa[4] = {q.x,q.y,q.z,q.w};
            float ka[4] = {k.x,k.y,k.z,k.w};
            #pragma unroll
            for (int i = 0; i < 4; i++)
                #pragma unroll
                for (int j = 0; j < 4; j++)
                    acc[i][j] = fmaf(qa[i], ka[j], acc[i][j]);
        }
    }
    float* dst = g_Sca + ((size_t)(bh*16 + slice)*64)*64;
    #pragma unroll
    for (int i = 0; i < 4; i++)
        *(float4*)&dst[(i0+i)*64 + j0] = make_float4(acc[i][0],acc[i][1],acc[i][2],acc[i][3]);
}

__global__ void ca_reduce(const float* __restrict__ temp)
{
    int bh = blockIdx.x;
    int h  = bh & 7;
    int i  = threadIdx.x;
    float scale = 0.125f * temp[h];
    float row[64];
    #pragma unroll
    for (int j = 0; j < 64; j++) {
        float s = 0.f;
        #pragma unroll
        for (int p = 0; p < 16; p++)
            s += g_Sca[((size_t)(bh*16+p)*64 + i)*64 + j];
        row[j] = s * scale;
    }
    float m = row[0];
    #pragma unroll
    for (int j = 1; j < 64; j++) m = fmaxf(m, row[j]);
    float sum = 0.f;
    #pragma unroll
    for (int j = 0; j < 64; j++) { row[j] = __expf(row[j]-m); sum += row[j]; }
    float inv = 1.f / sum;
    #pragma unroll
    for (int j = 0; j < 64; j++)
        g_Pca[((size_t)bh*64 + i)*64 + j] = row[j]*inv;
}

__global__ __launch_bounds__(256) void ca_out(float* __restrict__ out)
{
    __shared__ float Pts[64][68];
    __shared__ float Vt[64][68];
    int mt = blockIdx.x;
    int bh = blockIdx.y;
    int b = bh >> 3, h = bh & 7;
    int tid = threadIdx.x;
    {
        int i  = tid & 63;
        int jc = (tid >> 6) << 4;
        const float* pp = g_Pca + ((size_t)bh*64 + i)*64 + jc;
        #pragma unroll
        for (int t = 0; t < 4; t++) {
            float4 v = *(const float4*)(pp + t*4);
            Pts[jc+t*4+0][i] = v.x; Pts[jc+t*4+1][i] = v.y;
            Pts[jc+t*4+2][i] = v.z; Pts[jc+t*4+3][i] = v.w;
        }
    }
    {
        int mm = tid & 63;
        int jc = (tid >> 6) << 4;
        const float* vp = g_Pvc + ((size_t)b*NTOK + h*512)*512 + (size_t)(mt*64 + mm)*64 + jc;
        #pragma unroll
        for (int t = 0; t < 4; t++) {
            float4 v = *(const float4*)(vp + t*4);
            Vt[jc+t*4+0][mm] = v.x; Vt[jc+t*4+1][mm] = v.y;
            Vt[jc+t*4+2][mm] = v.z; Vt[jc+t*4+3][mm] = v.w;
        }
    }
    __syncthreads();
    int i0 = (tid >> 4) << 2, m0 = (tid & 15) << 2;
    float acc[4][4];
    #pragma unroll
    for (int i = 0; i < 4; i++)
        #pragma unroll
        for (int j = 0; j < 4; j++) acc[i][j] = 0.f;
    #pragma unroll 8
    for (int j = 0; j < 64; j++) {
        float4 p = *(const float4*)&Pts[j][i0];
        float4 v = *(const float4*)&Vt[j][m0];
        float pa[4] = {p.x,p.y,p.z,p.w};
        float va[4] = {v.x,v.y,v.z,v.w};
        #pragma unroll
        for (int i = 0; i < 4; i++)
            #pragma unroll
            for (int m = 0; m < 4; m++)
                acc[i][m] = fmaf(pa[i], va[m], acc[i][m]);
    }
    int rowoff  = mt >> 3;
    int colbase = (mt & 7)*64 + m0;
    #pragma unroll
    for (int i = 0; i < 4; i++) {
        int row = h*512 + (i0+i)*8 + rowoff;
        float* op = out + ((size_t)b*NTOK + row)*640 + colbase;
        *(float4*)op = make_float4(acc[i][0],acc[i][1],acc[i][2],acc[i][3]);
    }
}

// ============ spatial flash attention: 4 warps x 32 q-rows, 3 CTAs/SM ============
#define KSTR 72
#define VSTR 20
#define FKOFF(s) ((s)*4608)            // K stage: 64 x 72 floats
#define FVOFF(s) (13824 + (s)*1280)    // V stage: 64 x 20 floats
#define FSMEM ((13824 + 3840) * 4)     // 70656 bytes

__global__ __launch_bounds__(128, 3) void flash_mma(const float* __restrict__ t2,
                                                    float* __restrict__ out)
{
    extern __shared__ float sm[];
    int tid = threadIdx.x, w = tid >> 5, lane = tid & 31;
    int g = lane >> 2, tg = lane & 3;
    int qt = blockIdx.x, bh = blockIdx.y;
    int b = bh >> 3, h = bh & 7;
    const float* Qb = g_Pqs + ((size_t)b*NTOK + h*512)*512;   // tf32
    const float* Kb = g_Pks + ((size_t)b*NTOK + h*512)*512;   // tf32, col-permuted
    const float* Vb = g_Pvs + ((size_t)b*NTOK + h*512)*128;   // tf32
    float qscale = 0.125f * t2[h] * 1.4426950408889634f;

    // cp.async: K row = tid>>1, half (tid&1)*32 floats; V row = tid>>1, half (tid&1)*8 floats
    int kr = tid >> 1, kh = (tid & 1) << 5, vh = (tid & 1) << 3;
    uint32_t kdst[3], vdst[3];
    #pragma unroll
    for (int st = 0; st < 3; st++) {
        kdst[st] = smem_u32(sm + FKOFF(st) + kr*KSTR + kh);
        vdst[st] = smem_u32(sm + FVOFF(st) + kr*VSTR + vh);
    }
    const float* ksrc = Kb + (size_t)kr*64 + kh;
    const float* vsrc = Vb + (size_t)kr*16 + vh;

    // Q fragments: warp w owns rows q0..q0+31 (two m16 tiles)
    int q0 = w << 5;
    uint32_t qa[2][8][4];
    #pragma unroll
    for (int t = 0; t < 2; t++) {
        const float* qr0 = Qb + (size_t)(qt*128 + q0 + t*16 + g)*64;
        const float* qr1 = qr0 + 8*64;
        #pragma unroll
        for (int ks = 0; ks < 8; ks++) {
            qa[t][ks][0] = f2tf(qr0[ks*8 + tg]     * qscale);
            qa[t][ks][1] = f2tf(qr1[ks*8 + tg]     * qscale);
            qa[t][ks][2] = f2tf(qr0[ks*8 + tg + 4] * qscale);
            qa[t][ks][3] = f2tf(qr1[ks*8 + tg + 4] * qscale);
        }
    }

    float Ofr[2][2][4];
    #pragma unroll
    for (int t = 0; t < 2; t++)
        #pragma unroll
        for (int n = 0; n < 2; n++)
            #pragma unroll
            for (int e = 0; e < 4; e++) Ofr[t][n][e] = 0.f;
    float lsum[2][2] = {{0.f,0.f},{0.f,0.f}};
    int lsrc1 = (lane & 28) | (tg >> 1);
    int lsrc2 = lsrc1 + 2;
    bool oddt = (tg & 1);

    // prologue: chunks 0,1 -> stages 0,1
    #pragma unroll
    for (int i = 0; i < 8; i++) cpasync16(kdst[0] + i*16, ksrc + i*4);
    cpasync16(vdst[0], vsrc); cpasync16(vdst[0] + 16, vsrc + 4);
    CP_COMMIT();
    #pragma unroll
    for (int i = 0; i < 8; i++) cpasync16(kdst[1] + i*16, ksrc + 64*64 + i*4);
    cpasync16(vdst[1], vsrc + 64*16); cpasync16(vdst[1] + 16, vsrc + 64*16 + 4);
    CP_COMMIT();

    #pragma unroll 1
    for (int c = 0; c < 64; c++) {
        if (c + 1 < 64) { CP_WAIT1(); } else { CP_WAIT0(); }
        __syncthreads();
        if (c + 2 < 64) {
            int st = (c + 2) % 3;
            const float* kp = ksrc + (size_t)(c+2)*64*64;
            const float* vp = vsrc + (size_t)(c+2)*64*16;
            #pragma unroll
            for (int i = 0; i < 8; i++) cpasync16(kdst[st] + i*16, kp + i*4);
            cpasync16(vdst[st], vp); cpasync16(vdst[st] + 16, vp + 4);
            CP_COMMIT();
        }
        int st = c % 3;
        const uint32_t* Kc = (const uint32_t*)(sm + FKOFF(st));
        const uint32_t* Vc = (const uint32_t*)(sm + FVOFF(st));
        float rs[2][2] = {{0.f,0.f},{0.f,0.f}};

        #pragma unroll
        for (int nt = 0; nt < 8; nt++) {
            // ---- S tiles: two independent 16x8 chains share each K fragment ----
            float sfr[2][4];
            #pragma unroll
            for (int t = 0; t < 2; t++)
                sfr[t][0] = sfr[t][1] = sfr[t][2] = sfr[t][3] = 0.f;
            const uint32_t* krow = Kc + (nt*8 + g)*KSTR;
            #pragma unroll
            for (int ks = 0; ks < 8; ks++) {
                uint2 kb = *(const uint2*)(krow + ks*8 + 2*tg);  // permuted (tg, tg+4)
                mma8(sfr[0], qa[0][ks], kb.x, kb.y);
                mma8(sfr[1], qa[1][ks], kb.x, kb.y);
            }
            const uint32_t* v0 = Vc + (nt*8 + tg)*VSTR;
            const uint32_t* v1 = Vc + (nt*8 + tg + 4)*VSTR;
            uint32_t vb00 = v0[g], vb10 = v1[g], vb01 = v0[g+8], vb11 = v1[g+8];
            #pragma unroll
            for (int t = 0; t < 2; t++) {
                float p0 = ex2f(sfr[t][0]), p1 = ex2f(sfr[t][1]);
                float p2 = ex2f(sfr[t][2]), p3 = ex2f(sfr[t][3]);
                rs[t][0] += p0 + p1; rs[t][1] += p2 + p3;
                p0 = __uint_as_float(f2tf(p0)); p1 = __uint_as_float(f2tf(p1));
                p2 = __uint_as_float(f2tf(p2)); p3 = __uint_as_float(f2tf(p3));
                float w00 = __shfl_sync(0xffffffffu, p0, lsrc1);
                float w01 = __shfl_sync(0xffffffffu, p1, lsrc1);
                float w10 = __shfl_sync(0xffffffffu, p2, lsrc1);
                float w11 = __shfl_sync(0xffffffffu, p3, lsrc1);
                float w20 = __shfl_sync(0xffffffffu, p0, lsrc2);
                float w21 = __shfl_sync(0xffffffffu, p1, lsrc2);
                float w30 = __shfl_sync(0xffffffffu, p2, lsrc2);
                float w31 = __shfl_sync(0xffffffffu, p3, lsrc2);
                uint32_t ap[4];
                ap[0] = __float_as_uint(oddt ? w01 : w00);
                ap[1] = __float_as_uint(oddt ? w11 : w10);
                ap[2] = __float_as_uint(oddt ? w21 : w20);
                ap[3] = __float_as_uint(oddt ? w31 : w30);
                mma8(Ofr[t][0], ap, vb00, vb10);
                mma8(Ofr[t][1], ap, vb01, vb11);
            }
        }
        #pragma unroll
        for (int t = 0; t < 2; t++) {
            float r0 = rs[t][0], r1 = rs[t][1];
            r0 += __shfl_xor_sync(0xffffffffu, r0, 1);
            r0 += __shfl_xor_sync(0xffffffffu, r0, 2);
            r1 += __shfl_xor_sync(0xffffffffu, r1, 1);
            r1 += __shfl_xor_sync(0xffffffffu, r1, 2);
            lsum[t][0] += r0; lsum[t][1] += r1;
        }
    }

    #pragma unroll
    for (int t = 0; t < 2; t++) {
        float inv0 = 1.f / lsum[t][0], inv1 = 1.f / lsum[t][1];
        int n_g  = qt*128 + q0 + t*16 + g;
        int n_g8 = n_g + 8;
        float* op0 = out + ((size_t)b*NTOK + h*512 + (n_g  >> 3))*640 + 512 + (n_g  & 7)*16;
        float* op1 = out + ((size_t)b*NTOK + h*512 + (n_g8 >> 3))*640 + 512 + (n_g8 & 7)*16;
        #pragma unroll
        for (int nh = 0; nh < 2; nh++) {
            int cbase = nh*8 + 2*tg;
            float2 a, c2;
            a.x  = Ofr[t][nh][0]*inv0; a.y  = Ofr[t][nh][1]*inv0;
            c2.x = Ofr[t][nh][2]*inv1; c2.y = Ofr[t][nh][3]*inv1;
            *(float2*)(op0 + cbase) = a;
            *(float2*)(op1 + cbase) = c2;
        }
    }
}

// =================== launch ===================
extern "C" void kernel_launch(void* const* d_in, const int* in_sizes, int n_in,
                              void* d_out, int out_size)
{
    const float* s_in = (const float*)d_in[0];
    const float* h_in = (const float*)d_in[1];
    const float* sh   = (const float*)d_in[2];
    const float* t1   = (const float*)d_in[3];
    const float* t2   = (const float*)d_in[4];
    const float* Wqc  = (const float*)d_in[5];
    const float* Wqs  = (const float*)d_in[6];
    const float* Wkc  = (const float*)d_in[7];
    const float* Wvc  = (const float*)d_in[8];
    const float* Wks  = (const float*)d_in[9];
    const float* Wvs  = (const float*)d_in[10];
    float* out = (float*)d_out;

    cudaFuncSetAttribute(flash_mma, cudaFuncAttributeMaxDynamicSharedMemorySize, FSMEM);
    cudaFuncSetAttribute(flash_mma, cudaFuncAttributePreferredSharedMemoryCarveout, 100);
    cudaFuncSetAttribute(gemm_proj_tc, cudaFuncAttributeMaxDynamicSharedMemorySize, GSMEM);
    cudaFuncSetAttribute(gemm_vs_tc, cudaFuncAttributeMaxDynamicSharedMemorySize, GSMEM);

    prep<<<(SEGT + 255) / 256, 256>>>(
        (const float4*)s_in, (const float4*)sh, (const float4*)h_in,
        (const float4*)Wqc, (const float4*)Wqs, (const float4*)Wkc,
        (const float4*)Wvc, (const float4*)Wks, (const float4*)Wvs);
    gemm_proj_tc<<<dim3(20,64), 256, GSMEM>>>();
    gemm_vs_tc<<<64, 256, GSMEM>>>();
    flash_mma<<<dim3(32,16), 128, FSMEM>>>(t2, out);
    ca_scores<<<dim3(16,16), 256>>>();
    ca_reduce<<<16, 64>>>(t1);
    ca_out<<<dim3(64,16), 256>>>(out);
}

// round 10
// speedup vs baseline: 1.2889x; 1.2889x over previous
#include <cuda_runtime.h>
#include <math.h>
#include <stdint.h>

#define NB 2
#define NTOK 4096

__device__ float g_Pqc[8192*512];
__device__ float g_Pqs[8192*512];
__device__ float g_Pkc[8192*512];
__device__ float g_Pvc[8192*512];
__device__ uint32_t g_PksU[8192*256];   // K_s as bf16x2 pairs, slot-permuted
__device__ float g_Pvs[8192*128];
__device__ float g_Sca[16*16*64*64];
__device__ float g_Pca[16*64*64];
__device__ float g_ts [8192*512];
__device__ float g_tsh[8192*512];
__device__ float g_th [8192*128];
__device__ float g_tWqc[512*512];
__device__ float g_tWqs[512*512];
__device__ float g_tWkc[512*512];
__device__ float g_tWvc[512*512];
__device__ float g_tWks[512*512];
__device__ float g_tWvs[128*128];

// =================== helpers ===================
__device__ __forceinline__ uint32_t f2tf(float x) {
    uint32_t r; asm("cvt.rna.tf32.f32 %0, %1;" : "=r"(r) : "f"(x)); return r;
}
__device__ __forceinline__ uint32_t f2bf2(float lo, float hi) {
    uint32_t r; asm("cvt.rn.bf16x2.f32 %0, %1, %2;" : "=r"(r) : "f"(hi), "f"(lo)); return r;
}
__device__ __forceinline__ float ex2f(float x) {
    float r; asm("ex2.approx.ftz.f32 %0, %1;" : "=f"(r) : "f"(x)); return r;
}
__device__ __forceinline__ void mma8(float* d, const uint32_t* a, uint32_t b0, uint32_t b1) {
    asm volatile(
        "mma.sync.aligned.m16n8k8.row.col.f32.tf32.tf32.f32 "
        "{%0,%1,%2,%3},{%4,%5,%6,%7},{%8,%9},{%0,%1,%2,%3};"
        : "+f"(d[0]), "+f"(d[1]), "+f"(d[2]), "+f"(d[3])
        : "r"(a[0]), "r"(a[1]), "r"(a[2]), "r"(a[3]), "r"(b0), "r"(b1));
}
__device__ __forceinline__ void mma16bf(float* d, const uint32_t* a, uint32_t b0, uint32_t b1) {
    asm volatile(
        "mma.sync.aligned.m16n8k16.row.col.f32.bf16.bf16.f32 "
        "{%0,%1,%2,%3},{%4,%5,%6,%7},{%8,%9},{%0,%1,%2,%3};"
        : "+f"(d[0]), "+f"(d[1]), "+f"(d[2]), "+f"(d[3])
        : "r"(a[0]), "r"(a[1]), "r"(a[2]), "r"(a[3]), "r"(b0), "r"(b1));
}
__device__ __forceinline__ uint32_t smem_u32(const void* p) {
    uint32_t a;
    asm("{ .reg .u64 t; cvta.to.shared.u64 t, %1; cvt.u32.u64 %0, t; }" : "=r"(a) : "l"(p));
    return a;
}
__device__ __forceinline__ void cpasync16(uint32_t dst, const void* src) {
    asm volatile("cp.async.ca.shared.global [%0], [%1], 16;" :: "r"(dst), "l"(src));
}
#define CP_COMMIT() asm volatile("cp.async.commit_group;" ::: "memory")
#define CP_WAIT1()  asm volatile("cp.async.wait_group 1;" ::: "memory")
#define CP_WAIT0()  asm volatile("cp.async.wait_group 0;" ::: "memory")

// =================== prep: round all inputs to tf32 once ===================
#define SEG0 1048576
#define SEG1 2097152
#define SEG2 2359296
#define SEG3 2424832
#define SEG4 2490368
#define SEG5 2555904
#define SEG6 2621440
#define SEG7 2686976
#define SEGT 2691072
__global__ __launch_bounds__(256) void prep(
    const float4* __restrict__ s, const float4* __restrict__ sh, const float4* __restrict__ h,
    const float4* __restrict__ wqc, const float4* __restrict__ wqs, const float4* __restrict__ wkc,
    const float4* __restrict__ wvc, const float4* __restrict__ wks, const float4* __restrict__ wvs)
{
    int i = blockIdx.x * blockDim.x + threadIdx.x;
    if (i >= SEGT) return;
    const float4* src; float4* dst; int off;
    if      (i < SEG0) { src = s;   dst = (float4*)g_ts;   off = i; }
    else if (i < SEG1) { src = sh;  dst = (float4*)g_tsh;  off = i - SEG0; }
    else if (i < SEG2) { src = h;   dst = (float4*)g_th;   off = i - SEG1; }
    else if (i < SEG3) { src = wqc; dst = (float4*)g_tWqc; off = i - SEG2; }
    else if (i < SEG4) { src = wqs; dst = (float4*)g_tWqs; off = i - SEG3; }
    else if (i < SEG5) { src = wkc; dst = (float4*)g_tWkc; off = i - SEG4; }
    else if (i < SEG6) { src = wvc; dst = (float4*)g_tWvc; off = i - SEG5; }
    else if (i < SEG7) { src = wks; dst = (float4*)g_tWks; off = i - SEG6; }
    else               { src = wvs; dst = (float4*)g_tWvs; off = i - SEG7; }
    float4 v = src[off];
    dst[off] = make_float4(__uint_as_float(f2tf(v.x)), __uint_as_float(f2tf(v.y)),
                           __uint_as_float(f2tf(v.z)), __uint_as_float(f2tf(v.w)));
}

// =================== tf32 TC GEMM, 3-stage cp.async ===================
#define GSTG 2560
#define GSMEM (3*GSTG*2*4)

// mode: 0 = plain fp32 out, 1 = tf32-rounded out, 2 = bf16x2 pair-permuted out (K_s)
template<int K, int O>
__device__ __forceinline__ void gemm_tc_tile(const float* __restrict__ A,
                                             const float* __restrict__ W,
                                             float* __restrict__ C,
                                             int m0, int o0, int mode,
                                             float* dynsm)
{
    const int NC = K / 16;
    float* sA = dynsm;
    float* sW = dynsm + 3*GSTG;
    int tid = threadIdx.x, w = tid >> 5, lane = tid & 31;
    int g = lane >> 2, tg = lane & 3;
    int wm = w >> 2, wn = w & 3;
    int pr = tid >> 1, pc = (tid & 1) << 3;
    const float* Ap = A + (size_t)(m0 + pr) * K + pc;
    const float* Wp = W + (size_t)(o0 + pr) * K + pc;
    uint32_t sAb[3], sWb[3];
    #pragma unroll
    for (int st = 0; st < 3; st++) {
        sAb[st] = smem_u32(sA + st*GSTG + pr*20 + pc);
        sWb[st] = smem_u32(sW + st*GSTG + pr*20 + pc);
    }

    float acc[4][4][4];
    #pragma unroll
    for (int mt = 0; mt < 4; mt++)
        #pragma unroll
        for (int nt = 0; nt < 4; nt++)
            #pragma unroll
            for (int e = 0; e < 4; e++) acc[mt][nt][e] = 0.f;

    cpasync16(sAb[0],      Ap);      cpasync16(sAb[0] + 16, Ap + 4);
    cpasync16(sWb[0],      Wp);      cpasync16(sWb[0] + 16, Wp + 4);
    CP_COMMIT();
    cpasync16(sAb[1],      Ap + 16); cpasync16(sAb[1] + 16, Ap + 20);
    cpasync16(sWb[1],      Wp + 16); cpasync16(sWb[1] + 16, Wp + 20);
    CP_COMMIT();

    #pragma unroll 1
    for (int c = 0; c < NC; c++) {
        if (c + 1 < NC) { CP_WAIT1(); } else { CP_WAIT0(); }
        __syncthreads();
        if (c + 2 < NC) {
            int st = (c + 2) % 3;
            const float* ap = Ap + (c+2)*16;
            const float* wp = Wp + (c+2)*16;
            cpasync16(sAb[st],      ap); cpasync16(sAb[st] + 16, ap + 4);
            cpasync16(sWb[st],      wp); cpasync16(sWb[st] + 16, wp + 4);
            CP_COMMIT();
        }
        int st = c % 3;
        const uint32_t* cA = (const uint32_t*)(sA + st*GSTG);
        const uint32_t* cW = (const uint32_t*)(sW + st*GSTG);
        #pragma unroll
        for (int ks = 0; ks < 2; ks++) {
            uint32_t af[4][4], bf[4][2];
            #pragma unroll
            for (int mt = 0; mt < 4; mt++) {
                int rb = wm*64 + mt*16;
                af[mt][0] = cA[(rb+g  )*20 + ks*8 + tg];
                af[mt][1] = cA[(rb+g+8)*20 + ks*8 + tg];
                af[mt][2] = cA[(rb+g  )*20 + ks*8 + tg + 4];
                af[mt][3] = cA[(rb+g+8)*20 + ks*8 + tg + 4];
            }
            #pragma unroll
            for (int nt = 0; nt < 4; nt++) {
                int rb = wn*32 + nt*8 + g;
                bf[nt][0] = cW[rb*20 + ks*8 + tg];
                bf[nt][1] = cW[rb*20 + ks*8 + tg + 4];
            }
            #pragma unroll
            for (int mt = 0; mt < 4; mt++)
                #pragma unroll
                for (int nt = 0; nt < 4; nt++)
                    mma8(acc[mt][nt], af[mt], bf[nt][0], bf[nt][1]);
        }
    }
    #pragma unroll
    for (int mt = 0; mt < 4; mt++) {
        int r = m0 + wm*64 + mt*16 + g;
        #pragma unroll
        for (int nt = 0; nt < 4; nt++) {
            float v0 = acc[mt][nt][0], v1 = acc[mt][nt][1];
            float v2 = acc[mt][nt][2], v3 = acc[mt][nt][3];
            if (mode == 2) {
                // K_s: bf16x2 pair, permuted slot within 16-col group
                uint32_t lo = f2bf2(v0, v1);
                uint32_t hi = f2bf2(v2, v3);
                int c0  = o0 + wn*32 + nt*8 + 2*tg;
                int blk = c0 >> 6;              // key-within-flat-row
                int d   = c0 & 63;              // dim within key
                int slot = (nt & 1) ? (2*tg + 1) : (2*tg);
                uint32_t* kp = g_PksU + (size_t)r*256 + blk*32 + (d >> 4)*8 + slot;
                kp[0]     = lo;
                kp[8*256] = hi;
            } else {
                if (mode == 1) {
                    v0 = __uint_as_float(f2tf(v0)); v1 = __uint_as_float(f2tf(v1));
                    v2 = __uint_as_float(f2tf(v2)); v3 = __uint_as_float(f2tf(v3));
                }
                float* cp = C + (size_t)r*O + o0 + wn*32 + nt*8;
                *(float2*)(cp + 2*tg)       = make_float2(v0, v1);
                *(float2*)(cp + 8*O + 2*tg) = make_float2(v2, v3);
            }
        }
    }
}

__global__ __launch_bounds__(256, 2) void gemm_proj_tc()
{
    extern __shared__ float gdsm[];
    int job = blockIdx.x >> 2;
    int ot  = blockIdx.x & 3;
    int m0  = blockIdx.y << 7;
    const float* A; const float* W; float* C; int mode;
    switch (job) {
        case 0: A = g_tsh; W = g_tWqs; C = g_Pqs; mode = 0; break;
        case 1: A = g_tsh; W = g_tWkc; C = g_Pkc; mode = 0; break;
        case 2: A = g_tsh; W = g_tWvc; C = g_Pvc; mode = 0; break;
        case 3: A = g_tsh; W = g_tWks; C = (float*)g_PksU; mode = 2; break;
        default: A = g_ts; W = g_tWqc; C = g_Pqc; mode = 0; break;
    }
    gemm_tc_tile<512,512>(A, W, C, m0, ot << 7, mode, gdsm);
}

__global__ __launch_bounds__(256, 2) void gemm_vs_tc()
{
    extern __shared__ float gdsm[];
    gemm_tc_tile<128,128>(g_th, g_tWvs, g_Pvs, blockIdx.x << 7, 0, 1, gdsm);
}

// =================== channel attention (fp32, unchanged) ===================
__global__ __launch_bounds__(256) void ca_scores()
{
    __shared__ float Qs[32][68];
    __shared__ float Ks[32][68];
    int slice = blockIdx.x;
    int bh    = blockIdx.y;
    int b = bh >> 3, h = bh & 7;
    const float* Qc = g_Pqc + ((size_t)b*NTOK + h*512) * 512;
    const float* Kc = g_Pkc + ((size_t)b*NTOK + h*512) * 512;
    int tid = threadIdx.x;
    int lr = tid >> 3, lc = (tid & 7) << 3;
    int i0 = (tid >> 4) << 2, j0 = (tid & 15) << 2;
    float acc[4][4];
    #pragma unroll
    for (int i = 0; i < 4; i++)
        #pragma unroll
        for (int j = 0; j < 4; j++) acc[i][j] = 0.f;
    #pragma unroll 1
    for (int nt = 0; nt < 8; nt++) {
        int nb = slice*256 + (nt << 5);
        const float* qp = Qc + (size_t)(nb + lr)*64 + lc;
        const float* kp = Kc + (size_t)(nb + lr)*64 + lc;
        float4 q0 = *(const float4*)qp, q1 = *(const float4*)(qp+4);
        float4 k0 = *(const float4*)kp, k1 = *(const float4*)(kp+4);
        __syncthreads();
        *(float4*)&Qs[lr][lc] = q0; *(float4*)&Qs[lr][lc+4] = q1;
        *(float4*)&Ks[lr][lc] = k0; *(float4*)&Ks[lr][lc+4] = k1;
        __syncthreads();
        #pragma unroll 8
        for (int nn = 0; nn < 32; nn++) {
            float4 q = *(const float4*)&Qs[nn][i0];
            float4 k = *(const float4*)&Ks[nn][j0];
            float qa[4] = {q.x,q.y,q.z,q.w};
            float ka[4] = {k.x,k.y,k.z,k.w};
            #pragma unroll
            for (int i = 0; i < 4; i++)
                #pragma unroll
                for (int j = 0; j < 4; j++)
                    acc[i][j] = fmaf(qa[i], ka[j], acc[i][j]);
        }
    }
    float* dst = g_Sca + ((size_t)(bh*16 + slice)*64)*64;
    #pragma unroll
    for (int i = 0; i < 4; i++)
        *(float4*)&dst[(i0+i)*64 + j0] = make_float4(acc[i][0],acc[i][1],acc[i][2],acc[i][3]);
}

__global__ void ca_reduce(const float* __restrict__ temp)
{
    int bh = blockIdx.x;
    int h  = bh & 7;
    int i  = threadIdx.x;
    float scale = 0.125f * temp[h];
    float row[64];
    #pragma unroll
    for (int j = 0; j < 64; j++) {
        float s = 0.f;
        #pragma unroll
        for (int p = 0; p < 16; p++)
            s += g_Sca[((size_t)(bh*16+p)*64 + i)*64 + j];
        row[j] = s * scale;
    }
    float m = row[0];
    #pragma unroll
    for (int j = 1; j < 64; j++) m = fmaxf(m, row[j]);
    float sum = 0.f;
    #pragma unroll
    for (int j = 0; j < 64; j++) { row[j] = __expf(row[j]-m); sum += row[j]; }
    float inv = 1.f / sum;
    #pragma unroll
    for (int j = 0; j < 64; j++)
        g_Pca[((size_t)bh*64 + i)*64 + j] = row[j]*inv;
}

__global__ __launch_bounds__(256) void ca_out(float* __restrict__ out)
{
    __shared__ float Pts[64][68];
    __shared__ float Vt[64][68];
    int mt = blockIdx.x;
    int bh = blockIdx.y;
    int b = bh >> 3, h = bh & 7;
    int tid = threadIdx.x;
    {
        int i  = tid & 63;
        int jc = (tid >> 6) << 4;
        const float* pp = g_Pca + ((size_t)bh*64 + i)*64 + jc;
        #pragma unroll
        for (int t = 0; t < 4; t++) {
            float4 v = *(const float4*)(pp + t*4);
            Pts[jc+t*4+0][i] = v.x; Pts[jc+t*4+1][i] = v.y;
            Pts[jc+t*4+2][i] = v.z; Pts[jc+t*4+3][i] = v.w;
        }
    }
    {
        int mm = tid & 63;
        int jc = (tid >> 6) << 4;
        const float* vp = g_Pvc + ((size_t)b*NTOK + h*512)*512 + (size_t)(mt*64 + mm)*64 + jc;
        #pragma unroll
        for (int t = 0; t < 4; t++) {
            float4 v = *(const float4*)(vp + t*4);
            Vt[jc+t*4+0][mm] = v.x; Vt[jc+t*4+1][mm] = v.y;
            Vt[jc+t*4+2][mm] = v.z; Vt[jc+t*4+3][mm] = v.w;
        }
    }
    __syncthreads();
    int i0 = (tid >> 4) << 2, m0 = (tid & 15) << 2;
    float acc[4][4];
    #pragma unroll
    for (int i = 0; i < 4; i++)
        #pragma unroll
        for (int j = 0; j < 4; j++) acc[i][j] = 0.f;
    #pragma unroll 8
    for (int j = 0; j < 64; j++) {
        float4 p = *(const float4*)&Pts[j][i0];
        float4 v = *(const float4*)&Vt[j][m0];
        float pa[4] = {p.x,p.y,p.z,p.w};
        float va[4] = {v.x,v.y,v.z,v.w};
        #pragma unroll
        for (int i = 0; i < 4; i++)
            #pragma unroll
            for (int m = 0; m < 4; m++)
                acc[i][m] = fmaf(pa[i], va[m], acc[i][m]);
    }
    int rowoff  = mt >> 3;
    int colbase = (mt & 7)*64 + m0;
    #pragma unroll
    for (int i = 0; i < 4; i++) {
        int row = h*512 + (i0+i)*8 + rowoff;
        float* op = out + ((size_t)b*NTOK + row)*640 + colbase;
        *(float4*)op = make_float4(acc[i][0],acc[i][1],acc[i][2],acc[i][3]);
    }
}

// ============ spatial flash: bf16 logits (m16n8k16) + tf32 PV, P in regs ============
#define KSTRU 40
#define VSTR 20
#define FKOFFU(s) ((s)*2560)             // K stage: 64 keys x 40 u32
#define FVOFF(s)  (7680 + (s)*1280)      // V stage: 64 x 20 floats (float offset)
#define FSMEM ((7680 + 3*1280) * 4)      // 46080 bytes

__global__ __launch_bounds__(256, 2) void flash_mma(const float* __restrict__ t2,
                                                    float* __restrict__ out)
{
    extern __shared__ float sm[];
    uint32_t* smu = (uint32_t*)sm;
    int tid = threadIdx.x, w = tid >> 5, lane = tid & 31;
    int g = lane >> 2, tg = lane & 3;
    int qt = blockIdx.x, bh = blockIdx.y;
    int b = bh >> 3, h = bh & 7;
    const float*    Qb  = g_Pqs  + ((size_t)b*NTOK + h*512)*512;   // fp32
    const uint32_t* KbU = g_PksU + ((size_t)b*NTOK + h*512)*256;   // bf16x2 pairs
    const float*    Vb  = g_Pvs  + ((size_t)b*NTOK + h*512)*128;   // tf32
    float qscale = 0.125f * t2[h] * 1.4426950408889634f;

    // copies: K: 4 threads/key x 32B; V: 4 threads/key x 16B
    int kr = tid >> 2, kq = tid & 3;
    uint32_t kdst[3], vdst[3];
    #pragma unroll
    for (int st = 0; st < 3; st++) {
        kdst[st] = smem_u32(smu + FKOFFU(st) + kr*KSTRU + kq*8);
        vdst[st] = smem_u32(sm + FVOFF(st) + kr*VSTR + kq*4);
    }
    const uint32_t* ksrc = KbU + (size_t)kr*32 + kq*8;
    const float*    vsrc = Vb + (size_t)kr*16 + kq*4;

    // Q bf16 fragments (pre-scaled): 4 k-groups of 16 dims
    int q0 = w << 4;
    uint32_t qa[4][4];
    {
        const float* qr0 = Qb + (size_t)(qt*128 + q0 + g)*64;
        const float* qr1 = qr0 + 8*64;
        #pragma unroll
        for (int ks = 0; ks < 4; ks++) {
            int d0 = ks*16 + 2*tg;
            qa[ks][0] = f2bf2(qr0[d0]*qscale,   qr0[d0+1]*qscale);
            qa[ks][1] = f2bf2(qr1[d0]*qscale,   qr1[d0+1]*qscale);
            qa[ks][2] = f2bf2(qr0[d0+8]*qscale, qr0[d0+9]*qscale);
            qa[ks][3] = f2bf2(qr1[d0+8]*qscale, qr1[d0+9]*qscale);
        }
    }

    float Ofr[2][4];
    #pragma unroll
    for (int n = 0; n < 2; n++)
        #pragma unroll
        for (int e = 0; e < 4; e++) Ofr[n][e] = 0.f;
    float l0 = 0.f, l1 = 0.f;
    int lsrc1 = (lane & 28) | (tg >> 1);
    int lsrc2 = lsrc1 + 2;
    bool oddt = (tg & 1);

    // prologue: chunks 0,1 -> stages 0,1
    cpasync16(kdst[0], ksrc); cpasync16(kdst[0] + 16, ksrc + 4);
    cpasync16(vdst[0], vsrc);
    CP_COMMIT();
    cpasync16(kdst[1], ksrc + 64*32); cpasync16(kdst[1] + 16, ksrc + 64*32 + 4);
    cpasync16(vdst[1], vsrc + 64*16);
    CP_COMMIT();

    #pragma unroll 1
    for (int c = 0; c < 64; c++) {
        if (c + 1 < 64) { CP_WAIT1(); } else { CP_WAIT0(); }
        __syncthreads();
        if (c + 2 < 64) {
            int st = (c + 2) % 3;
            const uint32_t* kp = ksrc + (size_t)(c+2)*64*32;
            const float*    vp = vsrc + (size_t)(c+2)*64*16;
            cpasync16(kdst[st], kp); cpasync16(kdst[st] + 16, kp + 4);
            cpasync16(vdst[st], vp);
            CP_COMMIT();
        }
        int st = c % 3;
        const uint32_t* Kc = smu + FKOFFU(st);
        const uint32_t* Vc = (const uint32_t*)(sm + FVOFF(st));
        float rs0 = 0.f, rs1 = 0.f;

        #pragma unroll
        for (int nt = 0; nt < 8; nt++) {
            // ---- S tile: bf16 m16n8k16, 4 k-steps ----
            float sfr[4] = {0.f, 0.f, 0.f, 0.f};
            const uint32_t* krow = Kc + (nt*8 + g)*KSTRU;
            #pragma unroll
            for (int ks = 0; ks < 4; ks++) {
                uint2 kb = *(const uint2*)(krow + ks*8 + 2*tg);  // (pair tg, pair tg+4)
                mma16bf(sfr, qa[ks], kb.x, kb.y);
            }
            // ---- softmax (fixed shift) ----
            float p0 = ex2f(sfr[0]), p1 = ex2f(sfr[1]);
            float p2 = ex2f(sfr[2]), p3 = ex2f(sfr[3]);
            rs0 += p0 + p1; rs1 += p2 + p3;
            p0 = __uint_as_float(f2tf(p0)); p1 = __uint_as_float(f2tf(p1));
            p2 = __uint_as_float(f2tf(p2)); p3 = __uint_as_float(f2tf(p3));
            // ---- C-frag -> A-frag via quad shuffles ----
            float w00 = __shfl_sync(0xffffffffu, p0, lsrc1);
            float w01 = __shfl_sync(0xffffffffu, p1, lsrc1);
            float w10 = __shfl_sync(0xffffffffu, p2, lsrc1);
            float w11 = __shfl_sync(0xffffffffu, p3, lsrc1);
            float w20 = __shfl_sync(0xffffffffu, p0, lsrc2);
            float w21 = __shfl_sync(0xffffffffu, p1, lsrc2);
            float w30 = __shfl_sync(0xffffffffu, p2, lsrc2);
            float w31 = __shfl_sync(0xffffffffu, p3, lsrc2);
            uint32_t ap[4];
            ap[0] = __float_as_uint(oddt ? w01 : w00);
            ap[1] = __float_as_uint(oddt ? w11 : w10);
            ap[2] = __float_as_uint(oddt ? w21 : w20);
            ap[3] = __float_as_uint(oddt ? w31 : w30);
            // ---- O += P @ V (tf32) ----
            const uint32_t* v0 = Vc + (nt*8 + tg)*VSTR;
            const uint32_t* v1 = Vc + (nt*8 + tg + 4)*VSTR;
            mma8(Ofr[0], ap, v0[g],     v1[g]);
            mma8(Ofr[1], ap, v0[g + 8], v1[g + 8]);
        }
        rs0 += __shfl_xor_sync(0xffffffffu, rs0, 1);
        rs0 += __shfl_xor_sync(0xffffffffu, rs0, 2);
        rs1 += __shfl_xor_sync(0xffffffffu, rs1, 1);
        rs1 += __shfl_xor_sync(0xffffffffu, rs1, 2);
        l0 += rs0; l1 += rs1;
    }

    float inv0 = 1.f / l0, inv1 = 1.f / l1;
    int n_g  = qt*128 + q0 + g;
    int n_g8 = n_g + 8;
    float* op0 = out + ((size_t)b*NTOK + h*512 + (n_g  >> 3))*640 + 512 + (n_g  & 7)*16;
    float* op1 = out + ((size_t)b*NTOK + h*512 + (n_g8 >> 3))*640 + 512 + (n_g8 & 7)*16;
    #pragma unroll
    for (int nt = 0; nt < 2; nt++) {
        int cbase = nt*8 + 2*tg;
        float2 a, c2;
        a.x  = Ofr[nt][0]*inv0; a.y  = Ofr[nt][1]*inv0;
        c2.x = Ofr[nt][2]*inv1; c2.y = Ofr[nt][3]*inv1;
        *(float2*)(op0 + cbase) = a;
        *(float2*)(op1 + cbase) = c2;
    }
}

// =================== launch ===================
extern "C" void kernel_launch(void* const* d_in, const int* in_sizes, int n_in,
                              void* d_out, int out_size)
{
    const float* s_in = (const float*)d_in[0];
    const float* h_in = (const float*)d_in[1];
    const float* sh   = (const float*)d_in[2];
    const float* t1   = (const float*)d_in[3];
    const float* t2   = (const float*)d_in[4];
    const float* Wqc  = (const float*)d_in[5];
    const float* Wqs  = (const float*)d_in[6];
    const float* Wkc  = (const float*)d_in[7];
    const float* Wvc  = (const float*)d_in[8];
    const float* Wks  = (const float*)d_in[9];
    const float* Wvs  = (const float*)d_in[10];
    float* out = (float*)d_out;

    cudaFuncSetAttribute(flash_mma, cudaFuncAttributeMaxDynamicSharedMemorySize, FSMEM);
    cudaFuncSetAttribute(gemm_proj_tc, cudaFuncAttributeMaxDynamicSharedMemorySize, GSMEM);
    cudaFuncSetAttribute(gemm_vs_tc, cudaFuncAttributeMaxDynamicSharedMemorySize, GSMEM);

    prep<<<(SEGT + 255) / 256, 256>>>(
        (const float4*)s_in, (const float4*)sh, (const float4*)h_in,
        (const float4*)Wqc, (const float4*)Wqs, (const float4*)Wkc,
        (const float4*)Wvc, (const float4*)Wks, (const float4*)Wvs);
    gemm_proj_tc<<<dim3(20,64), 256, GSMEM>>>();
    gemm_vs_tc<<<64, 256, GSMEM>>>();
    flash_mma<<<dim3(32,16), 256, FSMEM>>>(t2, out);
    ca_scores<<<dim3(16,16), 256>>>();
    ca_reduce<<<16, 64>>>(t1);
    ca_out<<<dim3(64,16), 256>>>(out);
}

// round 11
// speedup vs baseline: 1.5091x; 1.1709x over previous
#include <cuda_runtime.h>
#include <math.h>
#include <stdint.h>

#define NB 2
#define NTOK 4096

__device__ float g_Pqc[8192*512];
__device__ float g_Pqs[8192*512];
__device__ float g_Pkc[8192*512];
__device__ float g_Pvc[8192*512];
__device__ uint32_t g_PksU[8192*256];   // K_s as bf16x2 pairs, slot-permuted
__device__ float g_Pvs[8192*128];       // V_s fp32 (unrounded)
__device__ uint32_t g_Vp[16*2048*16];   // V_s as bf16x2 key-pairs
__device__ float g_Vcs[16*16];          // V_s column sums per (b,h)
__device__ float g_Sca[16*16*64*64];
__device__ float g_Pca[16*64*64];
__device__ float g_ts [8192*512];
__device__ float g_tsh[8192*512];
__device__ float g_th [8192*128];
__device__ float g_tWqc[512*512];
__device__ float g_tWqs[512*512];
__device__ float g_tWkc[512*512];
__device__ float g_tWvc[512*512];
__device__ float g_tWks[512*512];
__device__ float g_tWvs[128*128];

// =================== helpers ===================
__device__ __forceinline__ uint32_t f2tf(float x) {
    uint32_t r; asm("cvt.rna.tf32.f32 %0, %1;" : "=r"(r) : "f"(x)); return r;
}
__device__ __forceinline__ uint32_t f2bf2(float lo, float hi) {
    uint32_t r; asm("cvt.rn.bf16x2.f32 %0, %1, %2;" : "=r"(r) : "f"(hi), "f"(lo)); return r;
}
__device__ __forceinline__ float ex2f(float x) {
    float r; asm("ex2.approx.ftz.f32 %0, %1;" : "=f"(r) : "f"(x)); return r;
}
__device__ __forceinline__ void mma8(float* d, const uint32_t* a, uint32_t b0, uint32_t b1) {
    asm volatile(
        "mma.sync.aligned.m16n8k8.row.col.f32.tf32.tf32.f32 "
        "{%0,%1,%2,%3},{%4,%5,%6,%7},{%8,%9},{%0,%1,%2,%3};"
        : "+f"(d[0]), "+f"(d[1]), "+f"(d[2]), "+f"(d[3])
        : "r"(a[0]), "r"(a[1]), "r"(a[2]), "r"(a[3]), "r"(b0), "r"(b1));
}
__device__ __forceinline__ void mma16bf(float* d, const uint32_t* a, uint32_t b0, uint32_t b1) {
    asm volatile(
        "mma.sync.aligned.m16n8k16.row.col.f32.bf16.bf16.f32 "
        "{%0,%1,%2,%3},{%4,%5,%6,%7},{%8,%9},{%0,%1,%2,%3};"
        : "+f"(d[0]), "+f"(d[1]), "+f"(d[2]), "+f"(d[3])
        : "r"(a[0]), "r"(a[1]), "r"(a[2]), "r"(a[3]), "r"(b0), "r"(b1));
}
__device__ __forceinline__ uint32_t smem_u32(const void* p) {
    uint32_t a;
    asm("{ .reg .u64 t; cvta.to.shared.u64 t, %1; cvt.u32.u64 %0, t; }" : "=r"(a) : "l"(p));
    return a;
}
__device__ __forceinline__ void cpasync16(uint32_t dst, const void* src) {
    asm volatile("cp.async.ca.shared.global [%0], [%1], 16;" :: "r"(dst), "l"(src));
}
#define CP_COMMIT() asm volatile("cp.async.commit_group;" ::: "memory")
#define CP_WAIT1()  asm volatile("cp.async.wait_group 1;" ::: "memory")
#define CP_WAIT0()  asm volatile("cp.async.wait_group 0;" ::: "memory")

// =================== prep: round all inputs to tf32 once ===================
#define SEG0 1048576
#define SEG1 2097152
#define SEG2 2359296
#define SEG3 2424832
#define SEG4 2490368
#define SEG5 2555904
#define SEG6 2621440
#define SEG7 2686976
#define SEGT 2691072
__global__ __launch_bounds__(256) void prep(
    const float4* __restrict__ s, const float4* __restrict__ sh, const float4* __restrict__ h,
    const float4* __restrict__ wqc, const float4* __restrict__ wqs, const float4* __restrict__ wkc,
    const float4* __restrict__ wvc, const float4* __restrict__ wks, const float4* __restrict__ wvs)
{
    int i = blockIdx.x * blockDim.x + threadIdx.x;
    if (i >= SEGT) return;
    const float4* src; float4* dst; int off;
    if      (i < SEG0) { src = s;   dst = (float4*)g_ts;   off = i; }
    else if (i < SEG1) { src = sh;  dst = (float4*)g_tsh;  off = i - SEG0; }
    else if (i < SEG2) { src = h;   dst = (float4*)g_th;   off = i - SEG1; }
    else if (i < SEG3) { src = wqc; dst = (float4*)g_tWqc; off = i - SEG2; }
    else if (i < SEG4) { src = wqs; dst = (float4*)g_tWqs; off = i - SEG3; }
    else if (i < SEG5) { src = wkc; dst = (float4*)g_tWkc; off = i - SEG4; }
    else if (i < SEG6) { src = wvc; dst = (float4*)g_tWvc; off = i - SEG5; }
    else if (i < SEG7) { src = wks; dst = (float4*)g_tWks; off = i - SEG6; }
    else               { src = wvs; dst = (float4*)g_tWvs; off = i - SEG7; }
    float4 v = src[off];
    dst[off] = make_float4(__uint_as_float(f2tf(v.x)), __uint_as_float(f2tf(v.y)),
                           __uint_as_float(f2tf(v.z)), __uint_as_float(f2tf(v.w)));
}

// =================== tf32 TC GEMM, 3-stage cp.async ===================
#define GSTG 2560
#define GSMEM (3*GSTG*2*4)

// mode: 0 = plain fp32 out, 2 = bf16x2 pair-permuted out (K_s)
template<int K, int O>
__device__ __forceinline__ void gemm_tc_tile(const float* __restrict__ A,
                                             const float* __restrict__ W,
                                             float* __restrict__ C,
                                             int m0, int o0, int mode,
                                             float* dynsm)
{
    const int NC = K / 16;
    float* sA = dynsm;
    float* sW = dynsm + 3*GSTG;
    int tid = threadIdx.x, w = tid >> 5, lane = tid & 31;
    int g = lane >> 2, tg = lane & 3;
    int wm = w >> 2, wn = w & 3;
    int pr = tid >> 1, pc = (tid & 1) << 3;
    const float* Ap = A + (size_t)(m0 + pr) * K + pc;
    const float* Wp = W + (size_t)(o0 + pr) * K + pc;
    uint32_t sAb[3], sWb[3];
    #pragma unroll
    for (int st = 0; st < 3; st++) {
        sAb[st] = smem_u32(sA + st*GSTG + pr*20 + pc);
        sWb[st] = smem_u32(sW + st*GSTG + pr*20 + pc);
    }

    float acc[4][4][4];
    #pragma unroll
    for (int mt = 0; mt < 4; mt++)
        #pragma unroll
        for (int nt = 0; nt < 4; nt++)
            #pragma unroll
            for (int e = 0; e < 4; e++) acc[mt][nt][e] = 0.f;

    cpasync16(sAb[0],      Ap);      cpasync16(sAb[0] + 16, Ap + 4);
    cpasync16(sWb[0],      Wp);      cpasync16(sWb[0] + 16, Wp + 4);
    CP_COMMIT();
    cpasync16(sAb[1],      Ap + 16); cpasync16(sAb[1] + 16, Ap + 20);
    cpasync16(sWb[1],      Wp + 16); cpasync16(sWb[1] + 16, Wp + 20);
    CP_COMMIT();

    #pragma unroll 1
    for (int c = 0; c < NC; c++) {
        if (c + 1 < NC) { CP_WAIT1(); } else { CP_WAIT0(); }
        __syncthreads();
        if (c + 2 < NC) {
            int st = (c + 2) % 3;
            const float* ap = Ap + (c+2)*16;
            const float* wp = Wp + (c+2)*16;
            cpasync16(sAb[st],      ap); cpasync16(sAb[st] + 16, ap + 4);
            cpasync16(sWb[st],      wp); cpasync16(sWb[st] + 16, wp + 4);
            CP_COMMIT();
        }
        int st = c % 3;
        const uint32_t* cA = (const uint32_t*)(sA + st*GSTG);
        const uint32_t* cW = (const uint32_t*)(sW + st*GSTG);
        #pragma unroll
        for (int ks = 0; ks < 2; ks++) {
            uint32_t af[4][4], bf[4][2];
            #pragma unroll
            for (int mt = 0; mt < 4; mt++) {
                int rb = wm*64 + mt*16;
                af[mt][0] = cA[(rb+g  )*20 + ks*8 + tg];
                af[mt][1] = cA[(rb+g+8)*20 + ks*8 + tg];
                af[mt][2] = cA[(rb+g  )*20 + ks*8 + tg + 4];
                af[mt][3] = cA[(rb+g+8)*20 + ks*8 + tg + 4];
            }
            #pragma unroll
            for (int nt = 0; nt < 4; nt++) {
                int rb = wn*32 + nt*8 + g;
                bf[nt][0] = cW[rb*20 + ks*8 + tg];
                bf[nt][1] = cW[rb*20 + ks*8 + tg + 4];
            }
            #pragma unroll
            for (int mt = 0; mt < 4; mt++)
                #pragma unroll
                for (int nt = 0; nt < 4; nt++)
                    mma8(acc[mt][nt], af[mt], bf[nt][0], bf[nt][1]);
        }
    }
    #pragma unroll
    for (int mt = 0; mt < 4; mt++) {
        int r = m0 + wm*64 + mt*16 + g;
        #pragma unroll
        for (int nt = 0; nt < 4; nt++) {
            float v0 = acc[mt][nt][0], v1 = acc[mt][nt][1];
            float v2 = acc[mt][nt][2], v3 = acc[mt][nt][3];
            if (mode == 2) {
                uint32_t lo = f2bf2(v0, v1);
                uint32_t hi = f2bf2(v2, v3);
                int c0  = o0 + wn*32 + nt*8 + 2*tg;
                int blk = c0 >> 6;
                int d   = c0 & 63;
                int slot = (nt & 1) ? (2*tg + 1) : (2*tg);
                uint32_t* kp = g_PksU + (size_t)r*256 + blk*32 + (d >> 4)*8 + slot;
                kp[0]     = lo;
                kp[8*256] = hi;
            } else {
                float* cp = C + (size_t)r*O + o0 + wn*32 + nt*8;
                *(float2*)(cp + 2*tg)       = make_float2(v0, v1);
                *(float2*)(cp + 8*O + 2*tg) = make_float2(v2, v3);
            }
        }
    }
}

__global__ __launch_bounds__(256, 2) void gemm_proj_tc()
{
    extern __shared__ float gdsm[];
    int job = blockIdx.x >> 2;
    int ot  = blockIdx.x & 3;
    int m0  = blockIdx.y << 7;
    const float* A; const float* W; float* C; int mode;
    switch (job) {
        case 0: A = g_tsh; W = g_tWqs; C = g_Pqs; mode = 0; break;
        case 1: A = g_tsh; W = g_tWkc; C = g_Pkc; mode = 0; break;
        case 2: A = g_tsh; W = g_tWvc; C = g_Pvc; mode = 0; break;
        case 3: A = g_tsh; W = g_tWks; C = (float*)g_PksU; mode = 2; break;
        default: A = g_ts; W = g_tWqc; C = g_Pqc; mode = 0; break;
    }
    gemm_tc_tile<512,512>(A, W, C, m0, ot << 7, mode, gdsm);
}

__global__ __launch_bounds__(256, 2) void gemm_vs_tc()
{
    extern __shared__ float gdsm[];
    gemm_tc_tile<128,128>(g_th, g_tWvs, g_Pvs, blockIdx.x << 7, 0, 0, gdsm);
}

// ============ repack V_s to bf16 key-pairs + fp32 column sums ============
__global__ __launch_bounds__(256) void repack_v()
{
    __shared__ float4 red[256];
    int bh = blockIdx.x;
    int b = bh >> 3, h = bh & 7;
    const float* Vb = g_Pvs + ((size_t)b*NTOK + h*512)*128;
    uint32_t* Vp = g_Vp + (size_t)bh*32768;
    int tid = threadIdx.x;
    float4 part = make_float4(0.f, 0.f, 0.f, 0.f);
    #pragma unroll 4
    for (int i = tid; i < 8192; i += 256) {
        int key2 = i >> 2, cg = (i & 3) << 2;
        float4 v0 = *(const float4*)(Vb + (size_t)(2*key2)*16 + cg);
        float4 v1 = *(const float4*)(Vb + (size_t)(2*key2+1)*16 + cg);
        uint4 pk;
        pk.x = f2bf2(v0.x, v1.x);
        pk.y = f2bf2(v0.y, v1.y);
        pk.z = f2bf2(v0.z, v1.z);
        pk.w = f2bf2(v0.w, v1.w);
        *(uint4*)(Vp + (size_t)key2*16 + cg) = pk;
        part.x += v0.x + v1.x;
        part.y += v0.y + v1.y;
        part.z += v0.z + v1.z;
        part.w += v0.w + v1.w;
    }
    red[tid] = part;
    __syncthreads();
    if (tid < 4) {
        float4 ssum = make_float4(0.f, 0.f, 0.f, 0.f);
        for (int t = tid; t < 256; t += 4) {
            float4 v = red[t];
            ssum.x += v.x; ssum.y += v.y; ssum.z += v.z; ssum.w += v.w;
        }
        *(float4*)(g_Vcs + bh*16 + tid*4) = ssum;
    }
}

// =================== channel attention (fp32, unchanged) ===================
__global__ __launch_bounds__(256) void ca_scores()
{
    __shared__ float Qs[32][68];
    __shared__ float Ks[32][68];
    int slice = blockIdx.x;
    int bh    = blockIdx.y;
    int b = bh >> 3, h = bh & 7;
    const float* Qc = g_Pqc + ((size_t)b*NTOK + h*512) * 512;
    const float* Kc = g_Pkc + ((size_t)b*NTOK + h*512) * 512;
    int tid = threadIdx.x;
    int lr = tid >> 3, lc = (tid & 7) << 3;
    int i0 = (tid >> 4) << 2, j0 = (tid & 15) << 2;
    float acc[4][4];
    #pragma unroll
    for (int i = 0; i < 4; i++)
        #pragma unroll
        for (int j = 0; j < 4; j++) acc[i][j] = 0.f;
    #pragma unroll 1
    for (int nt = 0; nt < 8; nt++) {
        int nb = slice*256 + (nt << 5);
        const float* qp = Qc + (size_t)(nb + lr)*64 + lc;
        const float* kp = Kc + (size_t)(nb + lr)*64 + lc;
        float4 q0 = *(const float4*)qp, q1 = *(const float4*)(qp+4);
        float4 k0 = *(const float4*)kp, k1 = *(const float4*)(kp+4);
        __syncthreads();
        *(float4*)&Qs[lr][lc] = q0; *(float4*)&Qs[lr][lc+4] = q1;
        *(float4*)&Ks[lr][lc] = k0; *(float4*)&Ks[lr][lc+4] = k1;
        __syncthreads();
        #pragma unroll 8
        for (int nn = 0; nn < 32; nn++) {
            float4 q = *(const float4*)&Qs[nn][i0];
            float4 k = *(const float4*)&Ks[nn][j0];
            float qa[4] = {q.x,q.y,q.z,q.w};
            float ka[4] = {k.x,k.y,k.z,k.w};
            #pragma unroll
            for (int i = 0; i < 4; i++)
                #pragma unroll
                for (int j = 0; j < 4; j++)
                    acc[i][j] = fmaf(qa[i], ka[j], acc[i][j]);
        }
    }
    float* dst = g_Sca + ((size_t)(bh*16 + slice)*64)*64;
    #pragma unroll
    for (int i = 0; i < 4; i++)
        *(float4*)&dst[(i0+i)*64 + j0] = make_float4(acc[i][0],acc[i][1],acc[i][2],acc[i][3]);
}

__global__ void ca_reduce(const float* __restrict__ temp)
{
    int bh = blockIdx.x;
    int h  = bh & 7;
    int i  = threadIdx.x;
    float scale = 0.125f * temp[h];
    float row[64];
    #pragma unroll
    for (int j = 0; j < 64; j++) {
        float s = 0.f;
        #pragma unroll
        for (int p = 0; p < 16; p++)
            s += g_Sca[((size_t)(bh*16+p)*64 + i)*64 + j];
        row[j] = s * scale;
    }
    float m = row[0];
    #pragma unroll
    for (int j = 1; j < 64; j++) m = fmaxf(m, row[j]);
    float sum = 0.f;
    #pragma unroll
    for (int j = 0; j < 64; j++) { row[j] = __expf(row[j]-m); sum += row[j]; }
    float inv = 1.f / sum;
    #pragma unroll
    for (int j = 0; j < 64; j++)
        g_Pca[((size_t)bh*64 + i)*64 + j] = row[j]*inv;
}

__global__ __launch_bounds__(256) void ca_out(float* __restrict__ out)
{
    __shared__ float Pts[64][68];
    __shared__ float Vt[64][68];
    int mt = blockIdx.x;
    int bh = blockIdx.y;
    int b = bh >> 3, h = bh & 7;
    int tid = threadIdx.x;
    {
        int i  = tid & 63;
        int jc = (tid >> 6) << 4;
        const float* pp = g_Pca + ((size_t)bh*64 + i)*64 + jc;
        #pragma unroll
        for (int t = 0; t < 4; t++) {
            float4 v = *(const float4*)(pp + t*4);
            Pts[jc+t*4+0][i] = v.x; Pts[jc+t*4+1][i] = v.y;
            Pts[jc+t*4+2][i] = v.z; Pts[jc+t*4+3][i] = v.w;
        }
    }
    {
        int mm = tid & 63;
        int jc = (tid >> 6) << 4;
        const float* vp = g_Pvc + ((size_t)b*NTOK + h*512)*512 + (size_t)(mt*64 + mm)*64 + jc;
        #pragma unroll
        for (int t = 0; t < 4; t++) {
            float4 v = *(const float4*)(vp + t*4);
            Vt[jc+t*4+0][mm] = v.x; Vt[jc+t*4+1][mm] = v.y;
            Vt[jc+t*4+2][mm] = v.z; Vt[jc+t*4+3][mm] = v.w;
        }
    }
    __syncthreads();
    int i0 = (tid >> 4) << 2, m0 = (tid & 15) << 2;
    float acc[4][4];
    #pragma unroll
    for (int i = 0; i < 4; i++)
        #pragma unroll
        for (int j = 0; j < 4; j++) acc[i][j] = 0.f;
    #pragma unroll 8
    for (int j = 0; j < 64; j++) {
        float4 p = *(const float4*)&Pts[j][i0];
        float4 v = *(const float4*)&Vt[j][m0];
        float pa[4] = {p.x,p.y,p.z,p.w};
        float va[4] = {v.x,v.y,v.z,v.w};
        #pragma unroll
        for (int i = 0; i < 4; i++)
            #pragma unroll
            for (int m = 0; m < 4; m++)
                acc[i][m] = fmaf(pa[i], va[m], acc[i][m]);
    }
    int rowoff  = mt >> 3;
    int colbase = (mt & 7)*64 + m0;
    #pragma unroll
    for (int i = 0; i < 4; i++) {
        int row = h*512 + (i0+i)*8 + rowoff;
        float* op = out + ((size_t)b*NTOK + row)*640 + colbase;
        *(float4*)op = make_float4(acc[i][0],acc[i][1],acc[i][2],acc[i][3]);
    }
}

// ====== spatial flash: all-bf16 mma, 1+u softmax decomposition, no shuffles ======
#define KSTRU 40
#define FKOFFU(s) ((s)*2560)            // K stage: 64 keys x 40 u32
#define FVOFFU(s) (7680 + (s)*768)      // V stage: 32 pair-rows x 24 u32
#define FSMEM (9984 * 4)                // 39936 bytes

__global__ __launch_bounds__(256, 2) void flash_mma(const float* __restrict__ t2,
                                                    float* __restrict__ out)
{
    extern __shared__ float sm[];
    uint32_t* smu = (uint32_t*)sm;
    int tid = threadIdx.x, w = tid >> 5, lane = tid & 31;
    int g = lane >> 2, tg = lane & 3;
    int qt = blockIdx.x, bh = blockIdx.y;
    int b = bh >> 3, h = bh & 7;
    const float*    Qb  = g_Pqs  + ((size_t)b*NTOK + h*512)*512;
    const uint32_t* KbU = g_PksU + ((size_t)b*NTOK + h*512)*256;
    const uint32_t* Vpg = g_Vp + (size_t)bh*32768;
    float qscale = 0.125f * t2[h] * 1.4426950408889634f;

    int kr = tid >> 2, kq = tid & 3;
    uint32_t kdst[3], vdst[3];
    #pragma unroll
    for (int st = 0; st < 3; st++) {
        kdst[st] = smem_u32(smu + FKOFFU(st) + kr*KSTRU + kq*8);
        vdst[st] = smem_u32(smu + FVOFFU(st) + kr*24 + kq*4);   // valid for tid<128
    }
    const uint32_t* ksrc = KbU + (size_t)kr*32 + kq*8;
    const uint32_t* vsrc = Vpg + (size_t)kr*16 + kq*4;          // pair-row kr

    // Q bf16 fragments (pre-scaled)
    int q0 = w << 4;
    uint32_t qa[4][4];
    {
        const float* qr0 = Qb + (size_t)(qt*128 + q0 + g)*64;
        const float* qr1 = qr0 + 8*64;
        #pragma unroll
        for (int kd = 0; kd < 4; kd++) {
            int d0 = kd*16 + 2*tg;
            qa[kd][0] = f2bf2(qr0[d0]*qscale,   qr0[d0+1]*qscale);
            qa[kd][1] = f2bf2(qr1[d0]*qscale,   qr1[d0+1]*qscale);
            qa[kd][2] = f2bf2(qr0[d0+8]*qscale, qr0[d0+9]*qscale);
            qa[kd][3] = f2bf2(qr1[d0+8]*qscale, qr1[d0+9]*qscale);
        }
    }

    float Ofr[2][4];
    #pragma unroll
    for (int n = 0; n < 2; n++)
        #pragma unroll
        for (int e = 0; e < 4; e++) Ofr[n][e] = 0.f;
    float l0 = 0.f, l1 = 0.f;

    // prologue: chunks 0,1 -> stages 0,1
    cpasync16(kdst[0], ksrc); cpasync16(kdst[0] + 16, ksrc + 4);
    if (tid < 128) cpasync16(vdst[0], vsrc);
    CP_COMMIT();
    cpasync16(kdst[1], ksrc + 2048); cpasync16(kdst[1] + 16, ksrc + 2052);
    if (tid < 128) cpasync16(vdst[1], vsrc + 512);
    CP_COMMIT();

    #pragma unroll 1
    for (int c = 0; c < 64; c++) {
        if (c + 1 < 64) { CP_WAIT1(); } else { CP_WAIT0(); }
        __syncthreads();
        if (c + 2 < 64) {
            int st = (c + 2) % 3;
            const uint32_t* kp = ksrc + (size_t)(c+2)*2048;
            const uint32_t* vp = vsrc + (size_t)(c+2)*512;
            cpasync16(kdst[st], kp); cpasync16(kdst[st] + 16, kp + 4);
            if (tid < 128) cpasync16(vdst[st], vp);
            CP_COMMIT();
        }
        int st = c % 3;
        const uint32_t* Kc = smu + FKOFFU(st);
        const uint32_t* Vc = smu + FVOFFU(st);

        #pragma unroll
        for (int ks = 0; ks < 4; ks++) {
            // ---- two adjacent 16x8 S tiles (keys 16ks..16ks+16) ----
            float s0[4] = {0.f,0.f,0.f,0.f};
            float s1[4] = {0.f,0.f,0.f,0.f};
            const uint32_t* kr0 = Kc + (ks*16 + g)*KSTRU;
            const uint32_t* kr1 = kr0 + 8*KSTRU;
            #pragma unroll
            for (int kd = 0; kd < 4; kd++) {
                uint2 k0 = *(const uint2*)(kr0 + kd*8 + 2*tg);
                uint2 k1 = *(const uint2*)(kr1 + kd*8 + 2*tg);
                mma16bf(s0, qa[kd], k0.x, k0.y);
                mma16bf(s1, qa[kd], k1.x, k1.y);
            }
            // ---- u = exp2(s) - 1 ; accumulate row sums ----
            float u00 = ex2f(s0[0]) - 1.f, u01 = ex2f(s0[1]) - 1.f;
            float u02 = ex2f(s0[2]) - 1.f, u03 = ex2f(s0[3]) - 1.f;
            float u10 = ex2f(s1[0]) - 1.f, u11 = ex2f(s1[1]) - 1.f;
            float u12 = ex2f(s1[2]) - 1.f, u13 = ex2f(s1[3]) - 1.f;
            l0 += (u00 + u01) + (u10 + u11);
            l1 += (u02 + u03) + (u12 + u13);
            // ---- C-frag IS the A-frag for bf16 k16: just pack ----
            uint32_t ap[4];
            ap[0] = f2bf2(u00, u01);
            ap[1] = f2bf2(u02, u03);
            ap[2] = f2bf2(u10, u11);
            ap[3] = f2bf2(u12, u13);
            // ---- O += U @ V (bf16) ----
            const uint32_t* vr0 = Vc + (ks*8 + tg)*24;
            const uint32_t* vr1 = Vc + (ks*8 + tg + 4)*24;
            mma16bf(Ofr[0], ap, vr0[g],     vr1[g]);
            mma16bf(Ofr[1], ap, vr0[g + 8], vr1[g + 8]);
        }
    }
    l0 += __shfl_xor_sync(0xffffffffu, l0, 1);
    l0 += __shfl_xor_sync(0xffffffffu, l0, 2);
    l1 += __shfl_xor_sync(0xffffffffu, l1, 1);
    l1 += __shfl_xor_sync(0xffffffffu, l1, 2);

    float inv0 = 1.f / (4096.f + l0), inv1 = 1.f / (4096.f + l1);
    int n_g  = qt*128 + q0 + g;
    int n_g8 = n_g + 8;
    float* op0 = out + ((size_t)b*NTOK + h*512 + (n_g  >> 3))*640 + 512 + (n_g  & 7)*16;
    float* op1 = out + ((size_t)b*NTOK + h*512 + (n_g8 >> 3))*640 + 512 + (n_g8 & 7)*16;
    #pragma unroll
    for (int nt = 0; nt < 2; nt++) {
        int cbase = nt*8 + 2*tg;
        float2 cs = *(const float2*)(g_Vcs + bh*16 + cbase);
        float2 a, c2;
        a.x  = (cs.x + Ofr[nt][0])*inv0; a.y  = (cs.y + Ofr[nt][1])*inv0;
        c2.x = (cs.x + Ofr[nt][2])*inv1; c2.y = (cs.y + Ofr[nt][3])*inv1;
        *(float2*)(op0 + cbase) = a;
        *(float2*)(op1 + cbase) = c2;
    }
}

// =================== launch ===================
extern "C" void kernel_launch(void* const* d_in, const int* in_sizes, int n_in,
                              void* d_out, int out_size)
{
    const float* s_in = (const float*)d_in[0];
    const float* h_in = (const float*)d_in[1];
    const float* sh   = (const float*)d_in[2];
    const float* t1   = (const float*)d_in[3];
    const float* t2   = (const float*)d_in[4];
    const float* Wqc  = (const float*)d_in[5];
    const float* Wqs  = (const float*)d_in[6];
    const float* Wkc  = (const float*)d_in[7];
    const float* Wvc  = (const float*)d_in[8];
    const float* Wks  = (const float*)d_in[9];
    const float* Wvs  = (const float*)d_in[10];
    float* out = (float*)d_out;

    cudaFuncSetAttribute(flash_mma, cudaFuncAttributeMaxDynamicSharedMemorySize, FSMEM);
    cudaFuncSetAttribute(gemm_proj_tc, cudaFuncAttributeMaxDynamicSharedMemorySize, GSMEM);
    cudaFuncSetAttribute(gemm_vs_tc, cudaFuncAttributeMaxDynamicSharedMemorySize, GSMEM);

    prep<<<(SEGT + 255) / 256, 256>>>(
        (const float4*)s_in, (const float4*)sh, (const float4*)h_in,
        (const float4*)Wqc, (const float4*)Wqs, (const float4*)Wkc,
        (const float4*)Wvc, (const float4*)Wks, (const float4*)Wvs);
    gemm_proj_tc<<<dim3(20,64), 256, GSMEM>>>();
    gemm_vs_tc<<<64, 256, GSMEM>>>();
    repack_v<<<16, 256>>>();
    flash_mma<<<dim3(32,16), 256, FSMEM>>>(t2, out);
    ca_scores<<<dim3(16,16), 256>>>();
    ca_reduce<<<16, 64>>>(t1);
    ca_out<<<dim3(64,16), 256>>>(out);
}